// round 15
// baseline (speedup 1.0000x reference)
#include <cuda_runtime.h>
#include <cuda_fp16.h>
#include <cstdint>

// Problem sizes (fixed by the dataset). All tensors are float32 on the wire.
static constexpr int M = 128;
static constexpr int K = 4096;
static constexpr int N = 11008;

static constexpr int BN = 128;     // per CTA -> 86 CTAs, single wave
static constexpr int GROUPS = 4;   // independent pipelines per CTA
static constexpr int BNG = 32;     // n per group
static constexpr int BK = 64;
static constexpr int STAGES = 4;
static constexpr int ITERS = K / BK;   // 64

static constexpr int A_BYTES = 128 * BK * 2;      // 16384 f16 per stage
static constexpr int B_BYTES = BK * BNG * 2;      // 4096  f16 per stage
static constexpr int SMEM_B0 = STAGES * A_BYTES;  // 65536 (A ring first)
static constexpr int SMEM_TOTAL = SMEM_B0 + GROUPS * STAGES * B_BYTES; // 131072

// masked-x scratch in fp16 (device global: no allocations allowed)
__device__ __half g_xm[M * K];

// ---------------------------------------------------------------------------
// Kernel 1: per-(16x64) block mean|x| threshold; write masked x as fp16
// ---------------------------------------------------------------------------
__global__ void mask_kernel(const float* __restrict__ x) {
    __shared__ float warp_part[4];
    __shared__ int flag;
    const int kb = blockIdx.x;      // 0..63
    const int mb = blockIdx.y;      // 0..7
    const int tid = threadIdx.x;    // 128 threads
    const int r  = tid >> 3;        // 0..15 row within block
    const int cg = tid & 7;         // 0..7 col-group (8 floats each)
    const float* p = x + (size_t)(mb * 16 + r) * K + kb * 64 + cg * 8;

    float4 v0 = *reinterpret_cast<const float4*>(p);
    float4 v1 = *reinterpret_cast<const float4*>(p + 4);
    float s = fabsf(v0.x) + fabsf(v0.y) + fabsf(v0.z) + fabsf(v0.w)
            + fabsf(v1.x) + fabsf(v1.y) + fabsf(v1.z) + fabsf(v1.w);
#pragma unroll
    for (int o = 16; o; o >>= 1) s += __shfl_xor_sync(0xffffffffu, s, o);
    if ((tid & 31) == 0) warp_part[tid >> 5] = s;
    __syncthreads();
    if (tid == 0) {
        float t = warp_part[0] + warp_part[1] + warp_part[2] + warp_part[3];
        flag = (t * (1.0f / 1024.0f)) > 0.8f ? 1 : 0;
    }
    __syncthreads();

    uint4 outv;
    if (flag) {
        __half2 h0 = __floats2half2_rn(v0.x, v0.y);
        __half2 h1 = __floats2half2_rn(v0.z, v0.w);
        __half2 h2 = __floats2half2_rn(v1.x, v1.y);
        __half2 h3 = __floats2half2_rn(v1.z, v1.w);
        outv.x = *reinterpret_cast<uint32_t*>(&h0);
        outv.y = *reinterpret_cast<uint32_t*>(&h1);
        outv.z = *reinterpret_cast<uint32_t*>(&h2);
        outv.w = *reinterpret_cast<uint32_t*>(&h3);
    } else {
        outv = make_uint4(0u, 0u, 0u, 0u);
    }
    *reinterpret_cast<uint4*>(g_xm + (size_t)(mb * 16 + r) * K + kb * 64 + cg * 8) = outv;
}

// ---------------------------------------------------------------------------
// PTX helpers (non-'a' features only)
// ---------------------------------------------------------------------------
__device__ __forceinline__ uint32_t smem_u32(const void* p) {
    uint32_t a;
    asm("{ .reg .u64 t; cvta.to.shared.u64 t, %1; cvt.u32.u64 %0, t; }" : "=r"(a) : "l"(p));
    return a;
}
__device__ __forceinline__ void cp_async16(uint32_t dst, const void* src) {
    asm volatile("cp.async.cg.shared.global [%0], [%1], 16;" :: "r"(dst), "l"(src) : "memory");
}
__device__ __forceinline__ void cp_commit() {
    asm volatile("cp.async.commit_group;" ::: "memory");
}
template <int NN>
__device__ __forceinline__ void cp_wait() {
    asm volatile("cp.async.wait_group %0;" :: "n"(NN) : "memory");
}
__device__ __forceinline__ void bar_sync(int id, int cnt) {
    asm volatile("bar.sync %0, %1;" :: "r"(id), "r"(cnt) : "memory");
}
__device__ __forceinline__ void ldsm_x4(uint32_t (&r)[4], uint32_t addr) {
    asm volatile("ldmatrix.sync.aligned.m8n8.x4.shared.b16 {%0,%1,%2,%3}, [%4];"
                 : "=r"(r[0]), "=r"(r[1]), "=r"(r[2]), "=r"(r[3]) : "r"(addr));
}
__device__ __forceinline__ void ldsm_x4_t(uint32_t (&r)[4], uint32_t addr) {
    asm volatile("ldmatrix.sync.aligned.m8n8.x4.trans.shared.b16 {%0,%1,%2,%3}, [%4];"
                 : "=r"(r[0]), "=r"(r[1]), "=r"(r[2]), "=r"(r[3]) : "r"(addr));
}
__device__ __forceinline__ void mma16816(float (&d)[4], const uint32_t (&a)[4],
                                         uint32_t b0, uint32_t b1) {
    asm volatile(
        "mma.sync.aligned.m16n8k16.row.col.f32.f16.f16.f32 "
        "{%0,%1,%2,%3}, {%4,%5,%6,%7}, {%8,%9}, {%0,%1,%2,%3};"
        : "+f"(d[0]), "+f"(d[1]), "+f"(d[2]), "+f"(d[3])
        : "r"(a[0]), "r"(a[1]), "r"(a[2]), "r"(a[3]), "r"(b0), "r"(b1));
}
__device__ __forceinline__ uint32_t pack_h2(float lo, float hi) {
    __half2 h = __floats2half2_rn(lo, hi);
    return *reinterpret_cast<uint32_t*>(&h);
}

// ---------------------------------------------------------------------------
// Kernel 2: FOUR independent pipelines per CTA + one shared A ring.
//   768 threads = 4 groups x (4 consumer warps + 2 producer warps).
//   Group g consumers: 128m x 32n slice (2x2 warps of 64m x 16n).
//   B ring per group (4 stages, 64B rows, chunk ^= (row&3) swizzle),
//   published via bar.sync(1+g, 192). Shared A ring (4 stages) loaded by
//   group-0 producers, published via bar.sync(5, 576) = 512 consumers +
//   g0's 64 producer threads. Rationale: per-SM throughput has scaled only
//   with the number of independent latency chains (R12); 2 -> 4 chains.
// ---------------------------------------------------------------------------
__global__ void __launch_bounds__(768, 1)
gemm_kernel(const float* __restrict__ w,
            const float* __restrict__ bias,
            float* __restrict__ out) {
    extern __shared__ char smem[];
    const uint32_t sb = smem_u32(smem);
    const int tid = threadIdx.x;
    const int grp = tid / 192;                // 0..3: pipeline group
    const int ltid = tid % 192;               // id within group
    const int lwid = ltid >> 5;               // 0..5 within group
    const int lane = tid & 31;
    const int n_grp = blockIdx.x * BN + grp * BNG;
    const uint32_t bbase = sb + SMEM_B0 + grp * (STAGES * B_BYTES);

    if (lwid >= 4) {
        // ---------------- producers (64 threads per group) ------------------
        const int ptid = ltid - 128;          // 0..63
        // B tile: [64 k-rows][32 n f16] = 64B rows, 4x16B chunks, chunk ^= (row&3)
        const int b_row = ptid >> 2;          // 0..15, +16*i
        const int fchk = ptid & 3;            // f16 chunk (covers f32 chunks 2*fchk, 2*fchk+1)
        const float* gB = w + (size_t)b_row * N + n_grp + fchk * 8;
        float4 bbuf[8];
        auto ldg_B = [&](int k0) {
#pragma unroll
            for (int i = 0; i < 4; i++) {
                const float* src = gB + (size_t)(k0 + i * 16) * N;
                bbuf[2 * i]     = *reinterpret_cast<const float4*>(src);
                bbuf[2 * i + 1] = *reinterpret_cast<const float4*>(src + 4);
            }
        };
        auto sts_B = [&](int stage) {
#pragma unroll
            for (int i = 0; i < 4; i++) {
                const int r = b_row + 16 * i;
                uint4 u;
                u.x = pack_h2(bbuf[2 * i].x,     bbuf[2 * i].y);
                u.y = pack_h2(bbuf[2 * i].z,     bbuf[2 * i].w);
                u.z = pack_h2(bbuf[2 * i + 1].x, bbuf[2 * i + 1].y);
                u.w = pack_h2(bbuf[2 * i + 1].z, bbuf[2 * i + 1].w);
                *reinterpret_cast<uint4*>(
                    smem + (bbase - sb) + stage * B_BYTES + r * 64 +
                    ((fchk ^ (r & 3)) << 4)) = u;
            }
        };

        if (grp == 0) {
            // A tile: [128 rows][64 f16] = 128B rows, 8 chunks, chunk ^= (row&7)
            const int a_row = ptid >> 3;      // 0..7, +8*i (16 steps)
            const int a_chk = ptid & 7;
            const __half* gA = g_xm + (size_t)a_row * K + a_chk * 8;
            const uint32_t sA_st = sb + a_row * 128 + ((a_chk ^ (a_row & 7)) << 4);
            auto load_A = [&](int stage, int k0) {
#pragma unroll
                for (int i = 0; i < 16; i++)
                    cp_async16(sA_st + stage * A_BYTES + i * (8 * 128),
                               gA + k0 + (size_t)i * 8 * K);
            };

            // prologue: A stages 0..2 in flight; B stages 0,1 stored, blk2 regs
#pragma unroll
            for (int s = 0; s < STAGES - 1; s++) { load_A(s, s * BK); cp_commit(); }
            ldg_B(0 * BK); sts_B(0);
            ldg_B(1 * BK); sts_B(1);
            ldg_B(2 * BK);

            for (int it = 0; it < ITERS; ++it) {
                cp_wait<STAGES - 2>();        // A of stage `it` arrived
                bar_sync(5, 576);             // publish A stage `it`
                bar_sync(1, 192);             // publish B stage `it` (g0)
                if (it + 3 < ITERS) load_A((it + 3) & (STAGES - 1), (it + 3) * BK);
                cp_commit();                  // unconditional: keeps group count
                if (it + 2 < ITERS) sts_B((it + 2) & (STAGES - 1));
                if (it + 3 < ITERS) ldg_B((it + 3) * BK);
            }
        } else {
            // groups 1-3: B only
            ldg_B(0 * BK); sts_B(0);
            ldg_B(1 * BK); sts_B(1);
            ldg_B(2 * BK);
            for (int it = 0; it < ITERS; ++it) {
                bar_sync(1 + grp, 192);       // publish B stage `it`
                if (it + 2 < ITERS) sts_B((it + 2) & (STAGES - 1));
                if (it + 3 < ITERS) ldg_B((it + 3) * BK);
            }
        }
        return;
    }

    // ---------------- consumers (4 warps/group, 2x2 of 64m x 16n tiles) -----
    const int wr = lwid >> 1;                 // 0/1 -> m offset
    const int wc = lwid & 1;                  // 0/1 -> n16 select
    const int m_w = wr * 64;

    float acc[4][4], acc2[4][4];              // 4 m16 x (first n8, second n8)
#pragma unroll
    for (int a = 0; a < 4; a++)
#pragma unroll
        for (int c = 0; c < 4; c++) { acc[a][c] = 0.f; acc2[a][c] = 0.f; }

    const int a_r = m_w + (lane & 15);        // ldmatrix A row
    const int a_c_hi = lane >> 4;             // k-chunk select
    const int b_k_lo = ((lane >> 3) & 1) * 8 + (lane & 7);  // ldmatrix B k row
    const int b_c_hi = lane >> 4;             // n-chunk select

    for (int it = 0; it < ITERS; ++it) {
        bar_sync(5, 576);                     // A stage `it` published
        bar_sync(1 + grp, 192);               // B stage `it` published
        const uint32_t stA = sb + (it & (STAGES - 1)) * A_BYTES;
        const uint32_t stB = bbase + (it & (STAGES - 1)) * B_BYTES;

#pragma unroll
        for (int ks = 0; ks < 4; ++ks) {
            uint32_t afr[4][4];
#pragma unroll
            for (int im = 0; im < 4; ++im) {
                const int row = a_r + im * 16;
                const int chk = (2 * ks + a_c_hi) ^ (row & 7);
                ldsm_x4(afr[im], stA + row * 128 + (chk << 4));
            }
            uint32_t bfr[4];
            const int krow = ks * 16 + b_k_lo;
            const int bchk = (wc * 2 + b_c_hi) ^ (krow & 3);
            ldsm_x4_t(bfr, stB + krow * 64 + (bchk << 4));
#pragma unroll
            for (int im = 0; im < 4; ++im) {
                mma16816(acc[im], afr[im], bfr[0], bfr[1]);
                mma16816(acc2[im], afr[im], bfr[2], bfr[3]);
            }
        }
    }

    // ---------------- epilogue: +bias, f32 store ----------------
    const int gr = lane >> 2;
    const int t = lane & 3;
#pragma unroll
    for (int im = 0; im < 4; ++im) {
        const int m0 = m_w + im * 16 + gr;
        const int n0 = n_grp + wc * 16 + 2 * t;
        const float2 bz0 = *reinterpret_cast<const float2*>(bias + n0);
        const float2 bz1 = *reinterpret_cast<const float2*>(bias + n0 + 8);
        float2* p0 = reinterpret_cast<float2*>(out + (size_t)m0 * N + n0);
        float2* p1 = reinterpret_cast<float2*>(out + (size_t)(m0 + 8) * N + n0);
        p0[0] = make_float2(acc[im][0] + bz0.x, acc[im][1] + bz0.y);
        p1[0] = make_float2(acc[im][2] + bz0.x, acc[im][3] + bz0.y);
        p0[4] = make_float2(acc2[im][0] + bz1.x, acc2[im][1] + bz1.y);
        p1[4] = make_float2(acc2[im][2] + bz1.x, acc2[im][3] + bz1.y);
    }
}

// ---------------------------------------------------------------------------
// Host launch
// ---------------------------------------------------------------------------
extern "C" void kernel_launch(void* const* d_in, const int* in_sizes, int n_in,
                              void* d_out, int out_size) {
    (void)in_sizes; (void)n_in; (void)out_size;
    const float* x    = (const float*)d_in[0];
    const float* w    = (const float*)d_in[1];
    const float* bias = (const float*)d_in[2];
    float* out        = (float*)d_out;

    mask_kernel<<<dim3(K / 64, M / 16), 128>>>(x);

    cudaFuncSetAttribute(gemm_kernel, cudaFuncAttributeMaxDynamicSharedMemorySize,
                         SMEM_TOTAL);
    gemm_kernel<<<N / BN, 768, SMEM_TOTAL>>>(w, bias, out);
}

// round 16
// speedup vs baseline: 1.2979x; 1.2979x over previous
#include <cuda_runtime.h>
#include <cuda_fp16.h>
#include <cstdint>

// Problem sizes (fixed by the dataset). All tensors are float32 on the wire.
static constexpr int M = 128;
static constexpr int K = 4096;
static constexpr int N = 11008;

static constexpr int BN = 128;     // per CTA (two n-64 halves) -> 86 CTAs
static constexpr int BNH = 64;     // per pipeline group
static constexpr int BK = 128;     // DOUBLED: halves barrier-iteration count
static constexpr int STAGES = 3;
static constexpr int ITERS = K / BK;   // 32

static constexpr int A_BYTES = 128 * BK * 2;          // 32768 f16 per stage (256B rows)
static constexpr int B_BYTES = BK * BNH * 2;          // 16384 f16 per stage (128B rows)
// smem: shared A ring [0, 96K), B ring g0 [96K, 144K), B ring g1 [144K, 192K)
static constexpr int SMEM_B0 = STAGES * A_BYTES;            // 98304
static constexpr int SMEM_B1 = SMEM_B0 + STAGES * B_BYTES;  // 147456
static constexpr int SMEM_TOTAL = SMEM_B1 + STAGES * B_BYTES; // 196608

// masked-x scratch in fp16 (device global: no allocations allowed)
__device__ __half g_xm[M * K];

// ---------------------------------------------------------------------------
// Kernel 1: per-(16x64) block mean|x| threshold; write masked x as fp16
// ---------------------------------------------------------------------------
__global__ void mask_kernel(const float* __restrict__ x) {
    __shared__ float warp_part[4];
    __shared__ int flag;
    const int kb = blockIdx.x;      // 0..63
    const int mb = blockIdx.y;      // 0..7
    const int tid = threadIdx.x;    // 128 threads
    const int r  = tid >> 3;        // 0..15 row within block
    const int cg = tid & 7;         // 0..7 col-group (8 floats each)
    const float* p = x + (size_t)(mb * 16 + r) * K + kb * 64 + cg * 8;

    float4 v0 = *reinterpret_cast<const float4*>(p);
    float4 v1 = *reinterpret_cast<const float4*>(p + 4);
    float s = fabsf(v0.x) + fabsf(v0.y) + fabsf(v0.z) + fabsf(v0.w)
            + fabsf(v1.x) + fabsf(v1.y) + fabsf(v1.z) + fabsf(v1.w);
#pragma unroll
    for (int o = 16; o; o >>= 1) s += __shfl_xor_sync(0xffffffffu, s, o);
    if ((tid & 31) == 0) warp_part[tid >> 5] = s;
    __syncthreads();
    if (tid == 0) {
        float t = warp_part[0] + warp_part[1] + warp_part[2] + warp_part[3];
        flag = (t * (1.0f / 1024.0f)) > 0.8f ? 1 : 0;
    }
    __syncthreads();

    uint4 outv;
    if (flag) {
        __half2 h0 = __floats2half2_rn(v0.x, v0.y);
        __half2 h1 = __floats2half2_rn(v0.z, v0.w);
        __half2 h2 = __floats2half2_rn(v1.x, v1.y);
        __half2 h3 = __floats2half2_rn(v1.z, v1.w);
        outv.x = *reinterpret_cast<uint32_t*>(&h0);
        outv.y = *reinterpret_cast<uint32_t*>(&h1);
        outv.z = *reinterpret_cast<uint32_t*>(&h2);
        outv.w = *reinterpret_cast<uint32_t*>(&h3);
    } else {
        outv = make_uint4(0u, 0u, 0u, 0u);
    }
    *reinterpret_cast<uint4*>(g_xm + (size_t)(mb * 16 + r) * K + kb * 64 + cg * 8) = outv;
}

// ---------------------------------------------------------------------------
// PTX helpers (non-'a' features only)
// ---------------------------------------------------------------------------
__device__ __forceinline__ uint32_t smem_u32(const void* p) {
    uint32_t a;
    asm("{ .reg .u64 t; cvta.to.shared.u64 t, %1; cvt.u32.u64 %0, t; }" : "=r"(a) : "l"(p));
    return a;
}
__device__ __forceinline__ void cp_async16(uint32_t dst, const void* src) {
    asm volatile("cp.async.cg.shared.global [%0], [%1], 16;" :: "r"(dst), "l"(src) : "memory");
}
__device__ __forceinline__ void cp_commit() {
    asm volatile("cp.async.commit_group;" ::: "memory");
}
template <int NN>
__device__ __forceinline__ void cp_wait() {
    asm volatile("cp.async.wait_group %0;" :: "n"(NN) : "memory");
}
__device__ __forceinline__ void bar_sync(int id, int cnt) {
    asm volatile("bar.sync %0, %1;" :: "r"(id), "r"(cnt) : "memory");
}
__device__ __forceinline__ void ldsm_x4(uint32_t (&r)[4], uint32_t addr) {
    asm volatile("ldmatrix.sync.aligned.m8n8.x4.shared.b16 {%0,%1,%2,%3}, [%4];"
                 : "=r"(r[0]), "=r"(r[1]), "=r"(r[2]), "=r"(r[3]) : "r"(addr));
}
__device__ __forceinline__ void ldsm_x4_t(uint32_t (&r)[4], uint32_t addr) {
    asm volatile("ldmatrix.sync.aligned.m8n8.x4.trans.shared.b16 {%0,%1,%2,%3}, [%4];"
                 : "=r"(r[0]), "=r"(r[1]), "=r"(r[2]), "=r"(r[3]) : "r"(addr));
}
__device__ __forceinline__ void mma16816(float (&d)[4], const uint32_t (&a)[4],
                                         uint32_t b0, uint32_t b1) {
    asm volatile(
        "mma.sync.aligned.m16n8k16.row.col.f32.f16.f16.f32 "
        "{%0,%1,%2,%3}, {%4,%5,%6,%7}, {%8,%9}, {%0,%1,%2,%3};"
        : "+f"(d[0]), "+f"(d[1]), "+f"(d[2]), "+f"(d[3])
        : "r"(a[0]), "r"(a[1]), "r"(a[2]), "r"(a[3]), "r"(b0), "r"(b1));
}
__device__ __forceinline__ uint32_t pack_h2(float lo, float hi) {
    __half2 h = __floats2half2_rn(lo, hi);
    return *reinterpret_cast<uint32_t*>(&h);
}

// ---------------------------------------------------------------------------
// Kernel 2: R13 topology (2 B pipelines + shared A ring) with BK=128.
//   512 threads = 2 groups x (4 consumer + 4 producer warps).
//   32 barrier-iterations instead of 64: tests the "constant period per
//   sync-iteration" model (all work-scaling knobs were neutral; only the
//   iteration structure ever moved the time).
//   A stage: 128 rows x 256B, chunk ^= (row & 15)  (16 chunks, conflict-free).
//   B stage: 128 k-rows x 128B, chunk ^= (krow & 7) (proven R12/R13 layout).
// ---------------------------------------------------------------------------
__global__ void __launch_bounds__(512, 1)
gemm_kernel(const float* __restrict__ w,
            const float* __restrict__ bias,
            float* __restrict__ out) {
    extern __shared__ char smem[];
    const uint32_t sb = smem_u32(smem);
    const int tid = threadIdx.x;
    const int grp = tid >> 8;                 // 0/1: pipeline group
    const int ltid = tid & 255;               // id within group
    const int lwid = ltid >> 5;               // 0..7 within group
    const int lane = tid & 31;
    const int n_half = blockIdx.x * BN + grp * BNH;
    const uint32_t bbase = sb + (grp ? SMEM_B1 : SMEM_B0);

    if (lwid >= 4) {
        // ---------------- producers (128 threads per group) -----------------
        const int ptid = ltid - 128;          // 0..127
        // B tile: [128 k-rows][64 n f16] = 128B rows, 8 chunks, chunk ^= (row&7)
        const int b_row = ptid >> 3;          // 0..15, +16*i (8 steps)
        const int b_chk = ptid & 7;
        const float* gB = w + (size_t)b_row * N + n_half + b_chk * 8;
        const uint32_t sB_st = bbase + b_row * 128 + ((b_chk ^ (b_row & 7)) << 4);

        float4 bbuf[16];                      // staged f32 B (8 rows x 8 f32)
        auto ldg_B = [&](int k0) {
#pragma unroll
            for (int i = 0; i < 8; i++) {
                const float* src = gB + (size_t)(k0 + i * 16) * N;
                bbuf[2 * i]     = *reinterpret_cast<const float4*>(src);
                bbuf[2 * i + 1] = *reinterpret_cast<const float4*>(src + 4);
            }
        };
        auto sts_B = [&](int stage) {
#pragma unroll
            for (int i = 0; i < 8; i++) {
                uint4 u;
                u.x = pack_h2(bbuf[2 * i].x,     bbuf[2 * i].y);
                u.y = pack_h2(bbuf[2 * i].z,     bbuf[2 * i].w);
                u.z = pack_h2(bbuf[2 * i + 1].x, bbuf[2 * i + 1].y);
                u.w = pack_h2(bbuf[2 * i + 1].z, bbuf[2 * i + 1].w);
                *reinterpret_cast<uint4*>(
                    smem + (sB_st - sb) + stage * B_BYTES + i * (16 * 128)) = u;
            }
        };

        if (grp == 0) {
            // A tile: [128 rows][128 f16] = 256B rows, 16 chunks, chunk ^= (row&15)
            const int a_row = ptid >> 4;      // 0..7, rows a_row + 8*i (16 steps)
            const int a_chk = ptid & 15;
            const __half* gA = g_xm + (size_t)a_row * K + a_chk * 8;
            auto load_A = [&](int stage, int k0) {
#pragma unroll
                for (int i = 0; i < 16; i++) {
                    const int row = a_row + 8 * i;
                    const uint32_t dst = sb + stage * A_BYTES + row * 256 +
                                         (uint32_t)((a_chk ^ (row & 15)) << 4);
                    cp_async16(dst, gA + k0 + (size_t)i * 8 * K);
                }
            };

            // prologue: A stages 0,1 in flight; B stages 0,1 stored, blk2 regs
            load_A(0, 0 * BK); cp_commit();
            load_A(1, 1 * BK); cp_commit();
            ldg_B(0 * BK); sts_B(0);
            ldg_B(1 * BK); sts_B(1);
            ldg_B(2 * BK);

            int s_w = 2;                      // ring slot of stage it+2
            for (int it = 0; it < ITERS; ++it) {
                cp_wait<1>();                 // A of stage `it` arrived
                bar_sync(3, 384);             // publish A stage `it`
                bar_sync(1, 256);             // publish B stage `it` (g0)
                if (it + 2 < ITERS) load_A(s_w, (it + 2) * BK);
                cp_commit();                  // unconditional: keeps group count
                if (it + 2 < ITERS) sts_B(s_w);
                if (it + 3 < ITERS) ldg_B((it + 3) * BK);
                if (++s_w == STAGES) s_w = 0;
            }
        } else {
            // group-1 producers: B only
            ldg_B(0 * BK); sts_B(0);
            ldg_B(1 * BK); sts_B(1);
            ldg_B(2 * BK);
            int s_w = 2;
            for (int it = 0; it < ITERS; ++it) {
                bar_sync(2, 256);             // publish B stage `it` (g1)
                if (it + 2 < ITERS) sts_B(s_w);
                if (it + 3 < ITERS) ldg_B((it + 3) * BK);
                if (++s_w == STAGES) s_w = 0;
            }
        }
        return;
    }

    // ---------------- consumers (4 warps/group, 2x2 of 64m x 32n tiles) -----
    const int wr = lwid >> 1;                 // 0/1 -> m offset
    const int wc = lwid & 1;                  // 0/1 -> n offset
    const int m_w = wr * 64;
    const int n_w = wc * 32;

    float acc[4][2][4];                       // first n8 of each n16 group
    float acc2[4][2][4];                      // second n8
#pragma unroll
    for (int a = 0; a < 4; a++)
#pragma unroll
        for (int b = 0; b < 2; b++)
#pragma unroll
            for (int c = 0; c < 4; c++) { acc[a][b][c] = 0.f; acc2[a][b][c] = 0.f; }

    const int a_r = m_w + (lane & 15);        // ldmatrix A row
    const int a_x = lane & 15;                // row&15 (im*16 invariant)
    const int a_c_hi = lane >> 4;             // k-chunk select
    const int b_k_lo = ((lane >> 3) & 1) * 8 + (lane & 7);  // ldmatrix B k row
    const int b_c_hi = lane >> 4;             // n-chunk select

    int s_cur = 0;
    for (int it = 0; it < ITERS; ++it) {
        bar_sync(3, 384);                     // A stage `it` published
        bar_sync(1 + grp, 256);               // B stage `it` published
        const uint32_t stA = sb + s_cur * A_BYTES;
        const uint32_t stB = bbase + s_cur * B_BYTES;
        if (++s_cur == STAGES) s_cur = 0;

#pragma unroll
        for (int ks = 0; ks < 8; ++ks) {      // 8 k16 steps (BK=128)
            uint32_t afr[4][4];
#pragma unroll
            for (int im = 0; im < 4; ++im) {
                const int row = a_r + im * 16;
                const int chk = (2 * ks + a_c_hi) ^ a_x;
                ldsm_x4(afr[im], stA + row * 256 + (chk << 4));
            }
#pragma unroll
            for (int in2 = 0; in2 < 2; ++in2) {
                uint32_t bfr[4];
                const int krow = ks * 16 + b_k_lo;
                const int chk = (4 * wc + 2 * in2 + b_c_hi) ^ (krow & 7);
                ldsm_x4_t(bfr, stB + krow * 128 + (chk << 4));
#pragma unroll
                for (int im = 0; im < 4; ++im) {
                    mma16816(acc[im][in2], afr[im], bfr[0], bfr[1]);
                    mma16816(acc2[im][in2], afr[im], bfr[2], bfr[3]);
                }
            }
        }
    }

    // ---------------- epilogue: +bias, f32 store ----------------
    const int gr = lane >> 2;
    const int t = lane & 3;
#pragma unroll
    for (int im = 0; im < 4; ++im) {
        const int m0 = m_w + im * 16 + gr;
#pragma unroll
        for (int in2 = 0; in2 < 2; ++in2) {
            const int n0 = n_half + n_w + in2 * 16 + 2 * t;
            const float2 bz0 = *reinterpret_cast<const float2*>(bias + n0);
            const float2 bz1 = *reinterpret_cast<const float2*>(bias + n0 + 8);
            float2* p0 = reinterpret_cast<float2*>(out + (size_t)m0 * N + n0);
            float2* p1 = reinterpret_cast<float2*>(out + (size_t)(m0 + 8) * N + n0);
            p0[0] = make_float2(acc[im][in2][0] + bz0.x, acc[im][in2][1] + bz0.y);
            p1[0] = make_float2(acc[im][in2][2] + bz0.x, acc[im][in2][3] + bz0.y);
            p0[4] = make_float2(acc2[im][in2][0] + bz1.x, acc2[im][in2][1] + bz1.y);
            p1[4] = make_float2(acc2[im][in2][2] + bz1.x, acc2[im][in2][3] + bz1.y);
        }
    }
}

// ---------------------------------------------------------------------------
// Host launch
// ---------------------------------------------------------------------------
extern "C" void kernel_launch(void* const* d_in, const int* in_sizes, int n_in,
                              void* d_out, int out_size) {
    (void)in_sizes; (void)n_in; (void)out_size;
    const float* x    = (const float*)d_in[0];
    const float* w    = (const float*)d_in[1];
    const float* bias = (const float*)d_in[2];
    float* out        = (float*)d_out;

    mask_kernel<<<dim3(K / 64, M / 16), 128>>>(x);

    cudaFuncSetAttribute(gemm_kernel, cudaFuncAttributeMaxDynamicSharedMemorySize,
                         SMEM_TOTAL);
    gemm_kernel<<<N / BN, 512, SMEM_TOTAL>>>(w, bias, out);
}